// round 15
// baseline (speedup 1.0000x reference)
#include <cuda_runtime.h>

#define BB 2
#define NN 8192
#define MM 2048
#define KNN 32
#define C0 64
#define C1 128
#define C2 256
#define CIN 67            // 3 + C0
#define OUT_OFS (BB*MM*3) // new_xyz written first, then out
#define NCELL 512         // 8x8x8 morton cells
#define NWORK 146         // worker blocks
#define WPB   73          // workers per batch
#define NT    256         // threads per block
#define NWARP 8           // FPS warps
#define PPT   32          // points per FPS thread

// ---------------- device scratch (no allocations allowed) ----------------
__device__ float g_W1t[CIN*C1];    // W1 transposed: [c][o]
__device__ float g_W2t[C1*C2];     // W2 transposed: [c][o]
__device__ int   g_sel[BB*MM];     // FPS ticket: original index + 1 (0 = not ready)
__device__ float g_p[BB*MM*C2];    // pooled features pre-BN
__device__ float g_scale[C2];
__device__ float g_shift[C2];

// ---------------- packed f32x2 helpers (bit-exact per-lane rn) ----------------
__device__ __forceinline__ unsigned long long pk2(float lo, float hi) {
    unsigned long long r;
    asm("mov.b64 %0, {%1, %2};" : "=l"(r) : "f"(lo), "f"(hi));
    return r;
}
__device__ __forceinline__ void upk2(unsigned long long v, float& lo, float& hi) {
    asm("mov.b64 {%0, %1}, %2;" : "=f"(lo), "=f"(hi) : "l"(v));
}
__device__ __forceinline__ unsigned long long addx2(unsigned long long a, unsigned long long b) {
    unsigned long long r;
    asm("add.rn.f32x2 %0, %1, %2;" : "=l"(r) : "l"(a), "l"(b));
    return r;
}
__device__ __forceinline__ unsigned long long mulx2(unsigned long long a, unsigned long long b) {
    unsigned long long r;
    asm("mul.rn.f32x2 %0, %1, %2;" : "=l"(r) : "l"(a), "l"(b));
    return r;
}

// 5-level shfl butterfly max on uint (replaces redux.max.u32)
__device__ __forceinline__ unsigned bfly_max32(unsigned v) {
    #pragma unroll
    for (int off = 16; off > 0; off >>= 1) {
        unsigned o = __shfl_xor_sync(0xffffffffu, v, off);
        v = (o > v) ? o : v;
    }
    return v;
}

__device__ __forceinline__ int cell_of(float x, float y, float z) {
    int ix = min(7, (int)(x * 8.0f));
    int iy = min(7, (int)(y * 8.0f));
    int iz = min(7, (int)(z * 8.0f));
    int c = 0;
    #pragma unroll
    for (int b = 0; b < 3; b++) {
        c |= ((ix >> b) & 1) << (3*b + 2);
        c |= ((iy >> b) & 1) << (3*b + 1);
        c |= ((iz >> b) & 1) << (3*b + 0);
    }
    return c;
}

// FPS smem (floats): sxs NN | sys NN | szs NN | sorig NN | comboT NN | hist NCELL | skey 2*8 ull | scur
#define FPS_SMEM_FLOATS (5*NN + NCELL + 32 + 8)

// ================= FUSED persistent kernel =================
__global__ void __launch_bounds__(NT, 1)
fused_kernel(const float* __restrict__ xyz, const float* __restrict__ x,
             const float* __restrict__ W1, const float* __restrict__ b1,
             const float* __restrict__ W2, const float* __restrict__ b2,
             float* __restrict__ out) {
    extern __shared__ float sm[];
    int tid = threadIdx.x;
    int lane = tid & 31, wid = tid >> 5;

    if (blockIdx.x < BB) {
        // ==================== FPS path: 8 warps, 32 pts/thread ====================
        float* sxs = sm;
        float* sys = sm + NN;
        float* szs = sm + 2*NN;
        int*  sorig  = (int*)(sm + 3*NN);
        int*  comboT = (int*)(sm + 4*NN);          // comboT[j*NT + tid], conflict-free
        int*  hist   = (int*)(sm + 5*NN);
        unsigned long long* skey = (unsigned long long*)(hist + NCELL);  // [2][8]
        int*  scur = (int*)(skey + 16);

        int b = blockIdx.x;
        const float* base = xyz + b*NN*3;

        if (tid == 0) *scur = 0;
        for (int i = tid; i < NCELL; i += NT) hist[i] = 0;
        __syncthreads();
        for (int i = tid; i < NN; i += NT) {
            float px = base[i*3+0], py = base[i*3+1], pz = base[i*3+2];
            atomicAdd(&hist[cell_of(px, py, pz)], 1);
        }
        __syncthreads();
        if (tid < 32) {
            int bs = tid*16;
            int loc[16]; int s = 0;
            #pragma unroll
            for (int k = 0; k < 16; k++) { loc[k] = hist[bs+k]; s += loc[k]; }
            int excl = s;
            #pragma unroll
            for (int off = 1; off < 32; off <<= 1) {
                int v = __shfl_up_sync(0xffffffffu, excl, off);
                if (lane >= off) excl += v;
            }
            excl -= s;
            int run = excl;
            #pragma unroll
            for (int k = 0; k < 16; k++) { hist[bs+k] = run; run += loc[k]; }
        }
        __syncthreads();
        for (int i = tid; i < NN; i += NT) {
            float px = base[i*3+0], py = base[i*3+1], pz = base[i*3+2];
            int c = cell_of(px, py, pz);
            int pos = atomicAdd(&hist[c], 1);
            sxs[pos] = px; sys[pos] = py; szs[pos] = pz; sorig[pos] = i;
        }
        __syncthreads();

        // ---- setup: packed register coords, dd, warp bbox, transposed combos ----
        int i0 = tid * PPT;
        unsigned long long pxp[PPT/2], pyp[PPT/2], pzp[PPT/2];
        float dd[PPT];
        float wlx, whx, wly, why_, wlz, whz;
        {
            float blx =  1e30f, bhx = -1e30f, bly =  1e30f, bhy = -1e30f;
            float blz =  1e30f, bhz = -1e30f;
            #pragma unroll
            for (int j = 0; j < PPT; j++) {
                float px = sxs[i0+j], py = sys[i0+j], pz = szs[i0+j];
                blx = fminf(blx, px); bhx = fmaxf(bhx, px);
                bly = fminf(bly, py); bhy = fmaxf(bhy, py);
                blz = fminf(blz, pz); bhz = fmaxf(bhz, pz);
                dd[j] = 1e10f;
                comboT[j*NT + tid] = (sorig[i0+j] << 13) | (i0 + j);
                if (sorig[i0+j] == 0) *scur = i0 + j;
            }
            #pragma unroll
            for (int q = 0; q < PPT/2; q++) {
                pxp[q] = pk2(sxs[i0+2*q], sxs[i0+2*q+1]);
                pyp[q] = pk2(sys[i0+2*q], sys[i0+2*q+1]);
                pzp[q] = pk2(szs[i0+2*q], szs[i0+2*q+1]);
            }
            wlx = blx; whx = bhx; wly = bly; why_ = bhy; wlz = blz; whz = bhz;
            #pragma unroll
            for (int off = 16; off > 0; off >>= 1) {
                wlx = fminf(wlx, __shfl_xor_sync(0xffffffffu, wlx, off));
                whx = fmaxf(whx, __shfl_xor_sync(0xffffffffu, whx, off));
                wly = fminf(wly, __shfl_xor_sync(0xffffffffu, wly, off));
                why_ = fmaxf(why_, __shfl_xor_sync(0xffffffffu, why_, off));
                wlz = fminf(wlz, __shfl_xor_sync(0xffffffffu, wlz, off));
                whz = fmaxf(whz, __shfl_xor_sync(0xffffffffu, whz, off));
            }
        }
        float tmax = 1e10f;                 // this thread's chunk max (always current)
        unsigned long long wkey = 0;        // cached warp key (exact while pruned)
        float wthresh = 1.0001e10f;

        __syncthreads();
        int cur = *scur;
        int curorig = 0;                    // FPS starts at original index 0

        float* outb = out + b*MM*3;
        for (int m = 0; m < MM; m++) {
            if (tid == 0) {
                outb[m*3+0] = sxs[cur];
                outb[m*3+1] = sys[cur];
                outb[m*3+2] = szs[cur];
                ((volatile int*)g_sel)[b*MM + m] = curorig + 1;  // publish ticket
            }
            if (m == MM-1) break;
            float lx = sxs[cur], ly = sys[cur], lz = szs[cur];
            int buf = m & 1;

            // warp-level bbox prune (1e-4 relative margin: provably no dd change)
            float wdx = fmaxf(fmaxf(wlx - lx, lx - whx), 0.f);
            float wdy = fmaxf(fmaxf(wly - ly, ly - why_), 0.f);
            float wdz = fmaxf(fmaxf(wlz - lz, lz - whz), 0.f);
            float wlb2 = fmaf(wdx, wdx, fmaf(wdy, wdy, wdz*wdz));
            if (wlb2 <= wthresh) {
                unsigned long long cX = pk2(-lx, -lx);
                unsigned long long cY = pk2(-ly, -ly);
                unsigned long long cZ = pk2(-lz, -lz);
                #pragma unroll
                for (int q = 0; q < PPT/2; q++) {
                    unsigned long long dx = addx2(pxp[q], cX);
                    unsigned long long dy = addx2(pyp[q], cY);
                    unsigned long long dz = addx2(pzp[q], cZ);
                    unsigned long long d2 = addx2(addx2(mulx2(dx,dx), mulx2(dy,dy)), mulx2(dz,dz));
                    float a, c;
                    upk2(d2, a, c);
                    dd[2*q]   = fminf(dd[2*q],   a);
                    dd[2*q+1] = fminf(dd[2*q+1], c);
                }
                // value-only chunk max: explicit tree, named temporaries
                float a0 = fmaxf(dd[0], dd[1]),   a1 = fmaxf(dd[2], dd[3]);
                float a2 = fmaxf(dd[4], dd[5]),   a3 = fmaxf(dd[6], dd[7]);
                float a4 = fmaxf(dd[8], dd[9]),   a5 = fmaxf(dd[10], dd[11]);
                float a6 = fmaxf(dd[12], dd[13]), a7 = fmaxf(dd[14], dd[15]);
                float a8 = fmaxf(dd[16], dd[17]), a9 = fmaxf(dd[18], dd[19]);
                float aa = fmaxf(dd[20], dd[21]), ab = fmaxf(dd[22], dd[23]);
                float ac = fmaxf(dd[24], dd[25]), ad = fmaxf(dd[26], dd[27]);
                float ae = fmaxf(dd[28], dd[29]), af = fmaxf(dd[30], dd[31]);
                float b0 = fmaxf(fmaxf(a0, a1), fmaxf(a2, a3));
                float b1_ = fmaxf(fmaxf(a4, a5), fmaxf(a6, a7));
                float b2_ = fmaxf(fmaxf(a8, a9), fmaxf(aa, ab));
                float b3 = fmaxf(fmaxf(ac, ad), fmaxf(ae, af));
                tmax = fmaxf(fmaxf(b0, b1_), fmaxf(b2_, b3));
                unsigned gwv = bfly_max32(__float_as_uint(tmax));
                // exact min-combo among lanes holding the warp max (conflict-free LDS)
                int best = 0x7FFFFFFF;
                if (__float_as_uint(tmax) == gwv) {
                    #pragma unroll
                    for (int j = 0; j < PPT; j++) {
                        if (__float_as_uint(dd[j]) == gwv)
                            best = min(best, comboT[j*NT + tid]);
                    }
                }
                unsigned nb = 0x7FFFFFFFu - (unsigned)best;   // 0 for non-winners
                unsigned gnb = bfly_max32(nb);
                wkey = ((unsigned long long)gwv << 32) | (unsigned long long)gnb;
                wthresh = __uint_as_float(gwv) * 1.0001f;
            }
            if (lane == 0) skey[buf*NWARP + wid] = wkey;
            __syncthreads();

            // single-barrier finalize: 3-level 64-bit lexicographic shfl butterfly
            {
                unsigned long long k = skey[buf*NWARP + (lane & (NWARP-1))];
                unsigned hi = (unsigned)(k >> 32);
                unsigned lo = (unsigned)k;
                #pragma unroll
                for (int off = 4; off > 0; off >>= 1) {
                    unsigned ohi = __shfl_xor_sync(0xffffffffu, hi, off);
                    unsigned olo = __shfl_xor_sync(0xffffffffu, lo, off);
                    if (ohi > hi || (ohi == hi && olo > lo)) { hi = ohi; lo = olo; }
                }
                unsigned combo = 0x7FFFFFFFu - lo;
                cur = (int)(combo & 0x1FFFu);
                curorig = (int)(combo >> 13) & 0x1FFF;
            }
        }
        return;
    }

    // ==================== worker path (256 threads) ====================
    int w = blockIdx.x - BB;       // 0..145
    int b = w & 1;
    int ws = w >> 1;               // 0..72

    float* sx = sm;
    float* sy = sm + NN;
    float* sz = sm + 2*NN;
    float* gT = sm + 3*NN;                 // [CIN][KNN]
    float* hS = gT + CIN*KNN;              // [C1][KNN]
    int*   sid = (int*)(hS + C1*KNN);      // [KNN]
    int*   soi = sid + KNN;

    const float* base = xyz + b*NN*3;
    for (int i = tid; i < NN; i += NT) {
        sx[i] = base[i*3+0]; sy[i] = base[i*3+1]; sz[i] = base[i*3+2];
    }
    for (int e = tid; e < C1*CIN; e += NT)
        g_W1t[(e % CIN)*C1 + (e / CIN)] = W1[e];
    for (int e = tid; e < C2*C1; e += NT)
        g_W2t[(e % C1)*C2 + (e / C1)] = W2[e];
    __syncthreads();

    for (int m = ws; m < MM; m += WPB) {
        if (tid == 0) {
            int v = ((volatile int*)g_sel)[b*MM + m];
            unsigned ns = 256;
            while (v == 0) {
                __nanosleep(ns);
                if (ns < 4096) ns <<= 1;
                v = ((volatile int*)g_sel)[b*MM + m];
            }
            *soi = (v - 1) & 0x1FFF;
        }
        __syncthreads();
        int oi = *soi;
        float cx = sx[oi], cy = sy[oi], cz = sz[oi];

        if (tid < 32) {
            int cnt = 0; int first = -1;
            for (int c = 0; c < NN/32; c++) {
                int i = c*32 + lane;
                float dx = sx[i]-cx, dy = sy[i]-cy, dz = sz[i]-cz;
                float d2 = __fadd_rn(__fadd_rn(__fmul_rn(dx,dx), __fmul_rn(dy,dy)),
                                     __fmul_rn(dz,dz));
                bool in = d2 < 0.01f;
                unsigned msk = __ballot_sync(0xffffffffu, in);
                if (first < 0 && msk) first = c*32 + (__ffs(msk) - 1);
                if (in) {
                    int slot = cnt + __popc(msk & ((1u << lane) - 1u));
                    if (slot < KNN) sid[slot] = i;
                }
                cnt += __popc(msk);
                if (cnt >= KNN) break;
            }
            if (first < 0) first = 0;
            for (int s2 = cnt + lane; s2 < KNN; s2 += 32) sid[s2] = first;
        }
        __syncthreads();

        for (int e = tid; e < CIN*KNN; e += NT) {
            int c = e >> 5, k = e & 31;
            int id = sid[k];
            float v;
            if      (c == 0) v = sx[id] - cx;
            else if (c == 1) v = sy[id] - cy;
            else if (c == 2) v = sz[id] - cz;
            else             v = x[(b*C0 + (c - 3))*NN + id];
            gT[c*KNN + k] = v;
        }
        __syncthreads();

        {
            int o = tid >> 1, kh = tid & 1, ko = kh * 16;
            float acc[16];
            float bb = b1[o];
            #pragma unroll
            for (int q = 0; q < 16; q++) acc[q] = bb;
            for (int c = 0; c < CIN; c++) {
                float wv = g_W1t[c*C1 + o];
                const float4* gp = (const float4*)&gT[c*KNN + ko];
                #pragma unroll
                for (int q = 0; q < 4; q++) {
                    float4 gv = gp[q];
                    acc[q*4+0] = fmaf(wv, gv.x, acc[q*4+0]);
                    acc[q*4+1] = fmaf(wv, gv.y, acc[q*4+1]);
                    acc[q*4+2] = fmaf(wv, gv.z, acc[q*4+2]);
                    acc[q*4+3] = fmaf(wv, gv.w, acc[q*4+3]);
                }
            }
            float4* hp = (float4*)&hS[o*KNN + ko];
            #pragma unroll
            for (int q = 0; q < 4; q++)
                hp[q] = make_float4(fmaxf(acc[q*4+0], 0.f), fmaxf(acc[q*4+1], 0.f),
                                    fmaxf(acc[q*4+2], 0.f), fmaxf(acc[q*4+3], 0.f));
        }
        __syncthreads();

        {
            float a2[32];
            #pragma unroll
            for (int k = 0; k < 32; k++) a2[k] = 0.f;
            #pragma unroll 4
            for (int c = 0; c < C1; c++) {
                float wv = g_W2t[c*C2 + tid];
                const float4* hp = (const float4*)&hS[c*KNN];
                #pragma unroll
                for (int q = 0; q < 8; q++) {
                    float4 hv = hp[q];
                    a2[q*4+0] = fmaf(wv, hv.x, a2[q*4+0]);
                    a2[q*4+1] = fmaf(wv, hv.y, a2[q*4+1]);
                    a2[q*4+2] = fmaf(wv, hv.z, a2[q*4+2]);
                    a2[q*4+3] = fmaf(wv, hv.w, a2[q*4+3]);
                }
            }
            float pm = a2[0];
            #pragma unroll
            for (int k = 1; k < 32; k++) pm = fmaxf(pm, a2[k]);
            g_p[(b*MM + m)*C2 + tid] = pm + b2[tid];
        }
        __syncthreads();
    }
}

// ---------------- BN stats + normalize fused: one block per channel ----------------
__global__ void __launch_bounds__(256)
bn_kernel(const float* __restrict__ gamma, const float* __restrict__ beta,
          float* __restrict__ out) {
    int o = blockIdx.x, t = threadIdx.x;
    float s = 0.f, s2 = 0.f;
    for (int i = t; i < BB*MM; i += 256) {
        float v = g_p[i*C2 + o];
        s += v; s2 = fmaf(v, v, s2);
    }
    __shared__ float ss[32], ssq[32];
    __shared__ float sscale, sshift;
    #pragma unroll
    for (int off = 16; off > 0; off >>= 1) {
        s  += __shfl_down_sync(0xffffffffu, s, off);
        s2 += __shfl_down_sync(0xffffffffu, s2, off);
    }
    if ((t & 31) == 0) { ss[t>>5] = s; ssq[t>>5] = s2; }
    __syncthreads();
    if (t < 32) {
        float a  = (t < 8) ? ss[t]  : 0.f;
        float aq = (t < 8) ? ssq[t] : 0.f;
        #pragma unroll
        for (int off = 4; off > 0; off >>= 1) {
            a  += __shfl_down_sync(0xffffffffu, a, off);
            aq += __shfl_down_sync(0xffffffffu, aq, off);
        }
        if (t == 0) {
            const float inv_n = 1.0f / (BB*MM);
            float mean = a * inv_n;
            float var  = fmaxf(aq * inv_n - mean*mean, 0.f);
            float rstd = rsqrtf(var + 1e-5f);
            float sc = rstd * gamma[o];
            sscale = sc;
            sshift = beta[o] - mean * sc;
        }
    }
    __syncthreads();
    float sc = sscale, sh = sshift;
    #pragma unroll 1
    for (int b = 0; b < BB; b++) {
        float* ob = out + OUT_OFS + (b*C2 + o)*MM;
        const float* pb = g_p + b*MM*C2 + o;
        for (int mm = t; mm < MM; mm += 256)
            ob[mm] = fmaf(pb[mm*C2], sc, sh);
    }
}

// ---------------- launch ----------------
extern "C" void kernel_launch(void* const* d_in, const int* in_sizes, int n_in,
                              void* d_out, int out_size) {
    const float* xyz   = (const float*)d_in[0];
    const float* x     = (const float*)d_in[1];
    const float* W1    = (const float*)d_in[2];
    const float* b1    = (const float*)d_in[3];
    const float* W2    = (const float*)d_in[4];
    const float* b2    = (const float*)d_in[5];
    const float* gamma = (const float*)d_in[6];
    const float* beta  = (const float*)d_in[7];
    float* out = (float*)d_out;

    size_t smem = (size_t)FPS_SMEM_FLOATS * 4;
    cudaFuncSetAttribute(fused_kernel, cudaFuncAttributeMaxDynamicSharedMemorySize, (int)smem);

    fused_kernel<<<BB + NWORK, NT, smem>>>(xyz, x, W1, b1, W2, b2, out);
    bn_kernel<<<C2, 256>>>(gamma, beta, out);
}

// round 16
// speedup vs baseline: 1.1254x; 1.1254x over previous
#include <cuda_runtime.h>

#define BB 2
#define NN 8192
#define MM 2048
#define KNN 32
#define C0 64
#define C1 128
#define C2 256
#define CIN 67            // 3 + C0
#define OUT_OFS (BB*MM*3) // new_xyz written first, then out
#define NCELL 512         // 8x8x8 morton cells
#define NWORK 146         // worker blocks
#define WPB   73          // workers per batch
#define NT    256         // threads per block
#define NWARP 8           // FPS warps
#define PPT   32          // points per FPS thread
#define NSEG  4           // prune segments per warp (256 sorted pts each)
#define SPT   8           // points per thread per segment

// ---------------- device scratch (no allocations allowed) ----------------
__device__ float g_W1t[CIN*C1];    // W1 transposed: [c][o]
__device__ float g_W2t[C1*C2];     // W2 transposed: [c][o]
__device__ int   g_sel[BB*MM];     // FPS ticket: original index + 1 (0 = not ready)
__device__ float g_p[BB*MM*C2];    // pooled features pre-BN

// ---------------- packed f32x2 helpers (bit-exact per-lane rn) ----------------
__device__ __forceinline__ unsigned long long pk2(float lo, float hi) {
    unsigned long long r;
    asm("mov.b64 %0, {%1, %2};" : "=l"(r) : "f"(lo), "f"(hi));
    return r;
}
__device__ __forceinline__ void upk2(unsigned long long v, float& lo, float& hi) {
    asm("mov.b64 {%0, %1}, %2;" : "=f"(lo), "=f"(hi) : "l"(v));
}
__device__ __forceinline__ unsigned long long addx2(unsigned long long a, unsigned long long b) {
    unsigned long long r;
    asm("add.rn.f32x2 %0, %1, %2;" : "=l"(r) : "l"(a), "l"(b));
    return r;
}
__device__ __forceinline__ unsigned long long mulx2(unsigned long long a, unsigned long long b) {
    unsigned long long r;
    asm("mul.rn.f32x2 %0, %1, %2;" : "=l"(r) : "l"(a), "l"(b));
    return r;
}

__device__ __forceinline__ int cell_of(float x, float y, float z) {
    int ix = min(7, (int)(x * 8.0f));
    int iy = min(7, (int)(y * 8.0f));
    int iz = min(7, (int)(z * 8.0f));
    int c = 0;
    #pragma unroll
    for (int b = 0; b < 3; b++) {
        c |= ((ix >> b) & 1) << (3*b + 2);
        c |= ((iy >> b) & 1) << (3*b + 1);
        c |= ((iz >> b) & 1) << (3*b + 0);
    }
    return c;
}

// FPS smem (floats): sxs NN | sys NN | szs NN | sorig NN | comboT NN | hist NCELL | skey 2*8 ull | scur
#define FPS_SMEM_FLOATS (5*NN + NCELL + 32 + 8)

// ================= FUSED persistent kernel =================
__global__ void __launch_bounds__(NT, 1)
fused_kernel(const float* __restrict__ xyz, const float* __restrict__ x,
             const float* __restrict__ W1, const float* __restrict__ b1,
             const float* __restrict__ W2, const float* __restrict__ b2,
             float* __restrict__ out) {
    extern __shared__ float sm[];
    int tid = threadIdx.x;
    int lane = tid & 31, wid = tid >> 5;

    if (blockIdx.x < BB) {
        // ========== FPS path: 8 warps, 32 pts/thread, 4 prune segments/warp ==========
        float* sxs = sm;
        float* sys = sm + NN;
        float* szs = sm + 2*NN;
        int*  sorig  = (int*)(sm + 3*NN);
        int*  comboT = (int*)(sm + 4*NN);          // comboT[j*NT + tid], conflict-free
        int*  hist   = (int*)(sm + 5*NN);
        unsigned long long* skey = (unsigned long long*)(hist + NCELL);  // [2][8]
        int*  scur = (int*)(skey + 16);

        int b = blockIdx.x;
        const float* base = xyz + b*NN*3;

        if (tid == 0) *scur = 0;
        for (int i = tid; i < NCELL; i += NT) hist[i] = 0;
        __syncthreads();
        for (int i = tid; i < NN; i += NT) {
            float px = base[i*3+0], py = base[i*3+1], pz = base[i*3+2];
            atomicAdd(&hist[cell_of(px, py, pz)], 1);
        }
        __syncthreads();
        if (tid < 32) {
            int bs = tid*16;
            int loc[16]; int s = 0;
            #pragma unroll
            for (int k = 0; k < 16; k++) { loc[k] = hist[bs+k]; s += loc[k]; }
            int excl = s;
            #pragma unroll
            for (int off = 1; off < 32; off <<= 1) {
                int v = __shfl_up_sync(0xffffffffu, excl, off);
                if (lane >= off) excl += v;
            }
            excl -= s;
            int run = excl;
            #pragma unroll
            for (int k = 0; k < 16; k++) { hist[bs+k] = run; run += loc[k]; }
        }
        __syncthreads();
        for (int i = tid; i < NN; i += NT) {
            float px = base[i*3+0], py = base[i*3+1], pz = base[i*3+2];
            int c = cell_of(px, py, pz);
            int pos = atomicAdd(&hist[c], 1);
            sxs[pos] = px; sys[pos] = py; szs[pos] = pz; sorig[pos] = i;
        }
        __syncthreads();

        // ---- setup: per-segment register coords + uniform seg bboxes ----
        // seg s of warp w covers sorted [w*1024 + s*256, +256); thread lane owns
        // 8 pts at w*1024 + s*256 + lane*8. dd[s*8+jj] maps to that point.
        int wb = wid * (PPT*32);               // warp base in sorted order
        unsigned long long pxp[PPT/2], pyp[PPT/2], pzp[PPT/2];
        float dd[PPT];
        float slx[NSEG], shx[NSEG], sly[NSEG], shy[NSEG], slz[NSEG], shz[NSEG];
        float tsmax[NSEG];
        {
            #pragma unroll
            for (int s = 0; s < NSEG; s++) {
                int ibase = wb + s*256 + lane*SPT;
                float blx =  1e30f, bhx = -1e30f, bly =  1e30f, bhy = -1e30f;
                float blz =  1e30f, bhz = -1e30f;
                #pragma unroll
                for (int jj = 0; jj < SPT; jj++) {
                    int idx = ibase + jj;
                    float px = sxs[idx], py = sys[idx], pz = szs[idx];
                    blx = fminf(blx, px); bhx = fmaxf(bhx, px);
                    bly = fminf(bly, py); bhy = fmaxf(bhy, py);
                    blz = fminf(blz, pz); bhz = fmaxf(bhz, pz);
                    int j = s*SPT + jj;
                    dd[j] = 1e10f;
                    comboT[j*NT + tid] = (sorig[idx] << 13) | idx;
                    if (sorig[idx] == 0) *scur = idx;
                }
                #pragma unroll
                for (int q = 0; q < SPT/2; q++) {
                    int idx = ibase + 2*q;
                    pxp[s*(SPT/2)+q] = pk2(sxs[idx], sxs[idx+1]);
                    pyp[s*(SPT/2)+q] = pk2(sys[idx], sys[idx+1]);
                    pzp[s*(SPT/2)+q] = pk2(szs[idx], szs[idx+1]);
                }
                // warp-uniform segment bbox via butterfly
                #pragma unroll
                for (int off = 16; off > 0; off >>= 1) {
                    blx = fminf(blx, __shfl_xor_sync(0xffffffffu, blx, off));
                    bhx = fmaxf(bhx, __shfl_xor_sync(0xffffffffu, bhx, off));
                    bly = fminf(bly, __shfl_xor_sync(0xffffffffu, bly, off));
                    bhy = fmaxf(bhy, __shfl_xor_sync(0xffffffffu, bhy, off));
                    blz = fminf(blz, __shfl_xor_sync(0xffffffffu, blz, off));
                    bhz = fmaxf(bhz, __shfl_xor_sync(0xffffffffu, bhz, off));
                }
                slx[s] = blx; shx[s] = bhx; sly[s] = bly; shy[s] = bhy;
                slz[s] = blz; shz[s] = bhz;
                tsmax[s] = 1e10f;
            }
        }
        float tmax = 1e10f;                 // max over all 32 dd (always current)
        unsigned long long wkey = 0;        // cached warp key (exact while all segs pruned)

        __syncthreads();
        int cur = *scur;
        int curorig = 0;

        float* outb = out + b*MM*3;
        for (int m = 0; m < MM; m++) {
            if (tid == 0) {
                outb[m*3+0] = sxs[cur];
                outb[m*3+1] = sys[cur];
                outb[m*3+2] = szs[cur];
                ((volatile int*)g_sel)[b*MM + m] = curorig + 1;  // publish ticket
            }
            if (m == MM-1) break;
            float lx = sxs[cur], ly = sys[cur], lz = szs[cur];
            int buf = m & 1;

            bool any_active = false;
            unsigned long long cX = pk2(-lx, -lx);
            unsigned long long cY = pk2(-ly, -ly);
            unsigned long long cZ = pk2(-lz, -lz);
            #pragma unroll
            for (int s = 0; s < NSEG; s++) {
                // segment bbox lower bound (warp-uniform values)
                float dxl = fmaxf(fmaxf(slx[s] - lx, lx - shx[s]), 0.f);
                float dyl = fmaxf(fmaxf(sly[s] - ly, ly - shy[s]), 0.f);
                float dzl = fmaxf(fmaxf(slz[s] - lz, lz - shz[s]), 0.f);
                float lb2 = fmaf(dxl, dxl, fmaf(dyl, dyl, dzl*dzl));
                // active if any lane's segment max-dd could be reduced
                if (__any_sync(0xffffffffu, lb2 <= tsmax[s] * 1.0001f)) {
                    any_active = true;
                    float smax = -1.f;
                    #pragma unroll
                    for (int q = 0; q < SPT/2; q++) {
                        int pq = s*(SPT/2) + q;
                        unsigned long long dx = addx2(pxp[pq], cX);
                        unsigned long long dy = addx2(pyp[pq], cY);
                        unsigned long long dz = addx2(pzp[pq], cZ);
                        unsigned long long d2 = addx2(addx2(mulx2(dx,dx), mulx2(dy,dy)), mulx2(dz,dz));
                        float a, c;
                        upk2(d2, a, c);
                        int j = s*SPT + 2*q;
                        float n0 = fminf(dd[j],   a);
                        float n1 = fminf(dd[j+1], c);
                        dd[j] = n0; dd[j+1] = n1;
                        smax = fmaxf(smax, fmaxf(n0, n1));
                    }
                    tsmax[s] = smax;
                }
            }
            if (any_active) {
                // recompute thread max and warp key (exact)
                float t0 = fmaxf(tsmax[0], tsmax[1]);
                float t1 = fmaxf(tsmax[2], tsmax[3]);
                tmax = fmaxf(t0, t1);
                unsigned gwv = __reduce_max_sync(0xffffffffu, __float_as_uint(tmax));
                int best = 0x7FFFFFFF;
                if (__float_as_uint(tmax) == gwv) {
                    #pragma unroll
                    for (int j = 0; j < PPT; j++) {
                        if (__float_as_uint(dd[j]) == gwv)
                            best = min(best, comboT[j*NT + tid]);
                    }
                }
                unsigned nb = 0x7FFFFFFFu - (unsigned)best;
                unsigned gnb = __reduce_max_sync(0xffffffffu, nb);
                wkey = ((unsigned long long)gwv << 32) | (unsigned long long)gnb;
            }
            if (lane == 0) skey[buf*NWARP + wid] = wkey;
            __syncthreads();

            // single-barrier finalize: each warp reduces the 8 keys redundantly
            {
                unsigned long long k = skey[buf*NWARP + (lane & (NWARP-1))];
                unsigned hi = (unsigned)(k >> 32);
                unsigned g2 = __reduce_max_sync(0xffffffffu, hi);
                unsigned lo = (hi == g2) ? (unsigned)k : 0u;
                unsigned glow = __reduce_max_sync(0xffffffffu, lo);
                unsigned combo = 0x7FFFFFFFu - glow;
                cur = (int)(combo & 0x1FFFu);
                curorig = (int)(combo >> 13) & 0x1FFF;
            }
        }
        return;
    }

    // ==================== worker path (256 threads) ====================
    int w = blockIdx.x - BB;
    int b = w & 1;
    int ws = w >> 1;

    float* sx = sm;
    float* sy = sm + NN;
    float* sz = sm + 2*NN;
    float* gT = sm + 3*NN;
    float* hS = gT + CIN*KNN;
    int*   sid = (int*)(hS + C1*KNN);
    int*   soi = sid + KNN;

    const float* base = xyz + b*NN*3;
    for (int i = tid; i < NN; i += NT) {
        sx[i] = base[i*3+0]; sy[i] = base[i*3+1]; sz[i] = base[i*3+2];
    }
    for (int e = tid; e < C1*CIN; e += NT)
        g_W1t[(e % CIN)*C1 + (e / CIN)] = W1[e];
    for (int e = tid; e < C2*C1; e += NT)
        g_W2t[(e % C1)*C2 + (e / C1)] = W2[e];
    __syncthreads();

    for (int m = ws; m < MM; m += WPB) {
        if (tid == 0) {
            int v = ((volatile int*)g_sel)[b*MM + m];
            unsigned ns = 256;
            while (v == 0) {
                __nanosleep(ns);
                if (ns < 4096) ns <<= 1;
                v = ((volatile int*)g_sel)[b*MM + m];
            }
            *soi = (v - 1) & 0x1FFF;
        }
        __syncthreads();
        int oi = *soi;
        float cx = sx[oi], cy = sy[oi], cz = sz[oi];

        if (tid < 32) {
            int cnt = 0; int first = -1;
            for (int c = 0; c < NN/32; c++) {
                int i = c*32 + lane;
                float dx = sx[i]-cx, dy = sy[i]-cy, dz = sz[i]-cz;
                float d2 = __fadd_rn(__fadd_rn(__fmul_rn(dx,dx), __fmul_rn(dy,dy)),
                                     __fmul_rn(dz,dz));
                bool in = d2 < 0.01f;
                unsigned msk = __ballot_sync(0xffffffffu, in);
                if (first < 0 && msk) first = c*32 + (__ffs(msk) - 1);
                if (in) {
                    int slot = cnt + __popc(msk & ((1u << lane) - 1u));
                    if (slot < KNN) sid[slot] = i;
                }
                cnt += __popc(msk);
                if (cnt >= KNN) break;
            }
            if (first < 0) first = 0;
            for (int s2 = cnt + lane; s2 < KNN; s2 += 32) sid[s2] = first;
        }
        __syncthreads();

        for (int e = tid; e < CIN*KNN; e += NT) {
            int c = e >> 5, k = e & 31;
            int id = sid[k];
            float v;
            if      (c == 0) v = sx[id] - cx;
            else if (c == 1) v = sy[id] - cy;
            else if (c == 2) v = sz[id] - cz;
            else             v = x[(b*C0 + (c - 3))*NN + id];
            gT[c*KNN + k] = v;
        }
        __syncthreads();

        {
            int o = tid >> 1, kh = tid & 1, ko = kh * 16;
            float acc[16];
            float bb = b1[o];
            #pragma unroll
            for (int q = 0; q < 16; q++) acc[q] = bb;
            for (int c = 0; c < CIN; c++) {
                float wv = g_W1t[c*C1 + o];
                const float4* gp = (const float4*)&gT[c*KNN + ko];
                #pragma unroll
                for (int q = 0; q < 4; q++) {
                    float4 gv = gp[q];
                    acc[q*4+0] = fmaf(wv, gv.x, acc[q*4+0]);
                    acc[q*4+1] = fmaf(wv, gv.y, acc[q*4+1]);
                    acc[q*4+2] = fmaf(wv, gv.z, acc[q*4+2]);
                    acc[q*4+3] = fmaf(wv, gv.w, acc[q*4+3]);
                }
            }
            float4* hp = (float4*)&hS[o*KNN + ko];
            #pragma unroll
            for (int q = 0; q < 4; q++)
                hp[q] = make_float4(fmaxf(acc[q*4+0], 0.f), fmaxf(acc[q*4+1], 0.f),
                                    fmaxf(acc[q*4+2], 0.f), fmaxf(acc[q*4+3], 0.f));
        }
        __syncthreads();

        {
            float a2[32];
            #pragma unroll
            for (int k = 0; k < 32; k++) a2[k] = 0.f;
            #pragma unroll 4
            for (int c = 0; c < C1; c++) {
                float wv = g_W2t[c*C2 + tid];
                const float4* hp = (const float4*)&hS[c*KNN];
                #pragma unroll
                for (int q = 0; q < 8; q++) {
                    float4 hv = hp[q];
                    a2[q*4+0] = fmaf(wv, hv.x, a2[q*4+0]);
                    a2[q*4+1] = fmaf(wv, hv.y, a2[q*4+1]);
                    a2[q*4+2] = fmaf(wv, hv.z, a2[q*4+2]);
                    a2[q*4+3] = fmaf(wv, hv.w, a2[q*4+3]);
                }
            }
            float pm = a2[0];
            #pragma unroll
            for (int k = 1; k < 32; k++) pm = fmaxf(pm, a2[k]);
            g_p[(b*MM + m)*C2 + tid] = pm + b2[tid];
        }
        __syncthreads();
    }
}

// ---------------- BN stats + normalize fused: one block per channel ----------------
__global__ void __launch_bounds__(256)
bn_kernel(const float* __restrict__ gamma, const float* __restrict__ beta,
          float* __restrict__ out) {
    int o = blockIdx.x, t = threadIdx.x;
    float s = 0.f, s2 = 0.f;
    for (int i = t; i < BB*MM; i += 256) {
        float v = g_p[i*C2 + o];
        s += v; s2 = fmaf(v, v, s2);
    }
    __shared__ float ss[32], ssq[32];
    __shared__ float sscale, sshift;
    #pragma unroll
    for (int off = 16; off > 0; off >>= 1) {
        s  += __shfl_down_sync(0xffffffffu, s, off);
        s2 += __shfl_down_sync(0xffffffffu, s2, off);
    }
    if ((t & 31) == 0) { ss[t>>5] = s; ssq[t>>5] = s2; }
    __syncthreads();
    if (t < 32) {
        float a  = (t < 8) ? ss[t]  : 0.f;
        float aq = (t < 8) ? ssq[t] : 0.f;
        #pragma unroll
        for (int off = 4; off > 0; off >>= 1) {
            a  += __shfl_down_sync(0xffffffffu, a, off);
            aq += __shfl_down_sync(0xffffffffu, aq, off);
        }
        if (t == 0) {
            const float inv_n = 1.0f / (BB*MM);
            float mean = a * inv_n;
            float var  = fmaxf(aq * inv_n - mean*mean, 0.f);
            float rstd = rsqrtf(var + 1e-5f);
            float sc = rstd * gamma[o];
            sscale = sc;
            sshift = beta[o] - mean * sc;
        }
    }
    __syncthreads();
    float sc = sscale, sh = sshift;
    #pragma unroll 1
    for (int b = 0; b < BB; b++) {
        float* ob = out + OUT_OFS + (b*C2 + o)*MM;
        const float* pb = g_p + b*MM*C2 + o;
        for (int mm = t; mm < MM; mm += 256)
            ob[mm] = fmaf(pb[mm*C2], sc, sh);
    }
}

// ---------------- launch ----------------
extern "C" void kernel_launch(void* const* d_in, const int* in_sizes, int n_in,
                              void* d_out, int out_size) {
    const float* xyz   = (const float*)d_in[0];
    const float* x     = (const float*)d_in[1];
    const float* W1    = (const float*)d_in[2];
    const float* b1    = (const float*)d_in[3];
    const float* W2    = (const float*)d_in[4];
    const float* b2    = (const float*)d_in[5];
    const float* gamma = (const float*)d_in[6];
    const float* beta  = (const float*)d_in[7];
    float* out = (float*)d_out;

    size_t smem = (size_t)FPS_SMEM_FLOATS * 4;
    cudaFuncSetAttribute(fused_kernel, cudaFuncAttributeMaxDynamicSharedMemorySize, (int)smem);

    fused_kernel<<<BB + NWORK, NT, smem>>>(xyz, x, W1, b1, W2, b2, out);
    bn_kernel<<<C2, 256>>>(gamma, beta, out);
}